// round 14
// baseline (speedup 1.0000x reference)
#include <cuda_runtime.h>
#include <cuda_bf16.h>
#include <cuda_fp16.h>
#include <cstdint>

#define T_LEN 2048
#define D_MODEL 1024
#define H_NUM 16
#define HS 64
#define CHUNK 128
#define NC 16
#define EPSF 1e-6f
#define SCP 80

// ---------------- scratch ----------------
__device__ float g_Sc [H_NUM * NC * HS * SCP];
__device__ __align__(16) __half g_sp[H_NUM * NC * HS * SCP];

__device__ __align__(16) __half g_qkv[3][H_NUM][T_LEN][HS];

__device__ __align__(16) __half g_xh[T_LEN * D_MODEL];
__device__ __align__(16) __half g_w1[3 * D_MODEL * D_MODEL];
__device__ __align__(16) __half g_w2[D_MODEL * D_MODEL];

__device__ __forceinline__ float phi(float x) {
    return x > 0.f ? x + 1.f : expf(x);
}
__device__ __forceinline__ uint32_t packh2(float a, float b) {
    return (uint32_t)__half_as_ushort(__float2half_rn(a)) |
           ((uint32_t)__half_as_ushort(__float2half_rn(b)) << 16);
}

// fused fp32 -> fp16 for x, w_qkv, w_out
#define CVT_X  524288
#define CVT_W1 786432
#define CVT_W2 262144
#define CVT_TOTAL (CVT_X + CVT_W1 + CVT_W2)
__global__ __launch_bounds__(256) void cvt_all(const float* __restrict__ x,
                                               const float* __restrict__ w1,
                                               const float* __restrict__ w2) {
    int i = blockIdx.x * 256 + threadIdx.x;
    const float* s;
    __half* d;
    int off;
    if (i < CVT_X)                { s = x;  d = g_xh; off = i; }
    else if (i < CVT_X + CVT_W1)  { s = w1; d = g_w1; off = i - CVT_X; }
    else                          { s = w2; d = g_w2; off = i - CVT_X - CVT_W1; }
    float4 v = ((const float4*)s)[off];
    ((uint2*)d)[off] = make_uint2(packh2(v.x, v.y), packh2(v.z, v.w));
}

// ---------------- mma helpers ----------------
__device__ __forceinline__ uint32_t smem_u32(const void* p) {
    uint32_t a;
    asm("{ .reg .u64 t; cvta.to.shared.u64 t, %1; cvt.u32.u64 %0, t; }" : "=r"(a) : "l"(p));
    return a;
}
__device__ __forceinline__ void ldsm4(uint32_t* r, uint32_t addr) {
    asm volatile("ldmatrix.sync.aligned.m8n8.x4.shared.b16 {%0,%1,%2,%3}, [%4];"
                 : "=r"(r[0]), "=r"(r[1]), "=r"(r[2]), "=r"(r[3]) : "r"(addr));
}
__device__ __forceinline__ void ldsm4t(uint32_t* r, uint32_t addr) {
    asm volatile("ldmatrix.sync.aligned.m8n8.x4.trans.shared.b16 {%0,%1,%2,%3}, [%4];"
                 : "=r"(r[0]), "=r"(r[1]), "=r"(r[2]), "=r"(r[3]) : "r"(addr));
}
__device__ __forceinline__ void mmaf16(float* d, const uint32_t* a, const uint32_t* b) {
    asm volatile("mma.sync.aligned.m16n8k16.row.col.f32.f16.f16.f32 "
                 "{%0,%1,%2,%3},{%4,%5,%6,%7},{%8,%9},{%0,%1,%2,%3};"
                 : "+f"(d[0]), "+f"(d[1]), "+f"(d[2]), "+f"(d[3])
                 : "r"(a[0]), "r"(a[1]), "r"(a[2]), "r"(a[3]), "r"(b[0]), "r"(b[1]));
}
#define CP16(dst, src) \
    asm volatile("cp.async.cg.shared.global [%0], [%1], 16;" :: "r"(dst), "l"(src) : "memory")
#define CP_COMMIT() asm volatile("cp.async.commit_group;" ::: "memory")
#define CP_WAIT0()  asm volatile("cp.async.wait_group 0;" ::: "memory")
#define CP_WAIT1()  asm volatile("cp.async.wait_group 1;" ::: "memory")

// ============================================================================
// unified fp16 GEMM: C = A[M][K] @ B[N][K]^T. CTA 64(M)x128(N), 8 warps 32x32
// (warp_m 2 x warp_n 4), BK=64, 3-stage, 2 CTA/SM.
// EPI=1: fused phi + fp16 store -> g_qkv (GEMM1). EPI=0: fp32 C (GEMM2).
// ============================================================================
#define FPITCH 144
#define GA (64 * FPITCH)                 /* 9216 */
#define GB (128 * FPITCH)                /* 18432 */
#define GSTG (GA + GB)                   /* 27648 */
#define GSM (3 * GSTG)                   /* 82944 */

template<int EPI>
__global__ __launch_bounds__(256, 2) void gemmT(
        const __half* __restrict__ A, const __half* __restrict__ B,
        float* __restrict__ C, int M, int N, int K) {
    extern __shared__ char smem[];
    const uint32_t sb = smem_u32(smem);

    const int tid = threadIdx.x;
    const int wid = tid >> 5, lid = tid & 31;
    const int warp_m = wid & 1, warp_n = wid >> 1;
    const int m0 = blockIdx.y * 64, n0 = blockIdx.x * 128;
    const int NKB = K >> 6;

    const int a_row  = lid & 15;
    const int a_koff = (lid >> 4) * 8;
    const int b_n    = (lid & 7) + ((lid >> 4) << 3);
    const int b_ko   = ((lid >> 3) & 1) * 8;
    const int g = lid >> 2, tg = lid & 3;

    float acc[2][4][4];
#pragma unroll
    for (int i = 0; i < 2; i++)
#pragma unroll
        for (int j = 0; j < 4; j++)
#pragma unroll
            for (int k = 0; k < 4; k++) acc[i][j][k] = 0.f;

    auto load_st = [&](uint32_t stg, int kb) {
#pragma unroll
        for (int j = 0; j < 6; j++) {
            int chunkid = tid + j * 256;               // 0..1535
            if (chunkid < 512) {
                int row = chunkid >> 3, c = chunkid & 7;
                CP16(stg + row * FPITCH + c * 16,
                     A + (size_t)(m0 + row) * K + kb * 64 + c * 8);
            } else {
                int cid = chunkid - 512;
                int row = cid >> 3, c = cid & 7;
                CP16(stg + GA + row * FPITCH + c * 16,
                     B + (size_t)(n0 + row) * K + kb * 64 + c * 8);
            }
        }
        CP_COMMIT();
    };

    load_st(sb, 0);
    load_st(sb + GSTG, 1);
    CP_WAIT1();
    __syncthreads();

#pragma unroll 1
    for (int kb = 0; kb < NKB; kb++) {
        if (kb + 2 < NKB) load_st(sb + ((kb + 2) % 3) * GSTG, kb + 2);

        const uint32_t stage = sb + (kb % 3) * GSTG;

#pragma unroll
        for (int ks = 0; ks < 4; ks++) {
            uint32_t af[2][4];
#pragma unroll
            for (int mt = 0; mt < 2; mt++) {
                uint32_t ao = (uint32_t)((warp_m * 32 + mt * 16 + a_row) * FPITCH +
                                         (ks * 16 + a_koff) * 2);
                ldsm4(af[mt], stage + ao);
            }
            uint32_t bf[2][4];
#pragma unroll
            for (int nh = 0; nh < 2; nh++) {
                uint32_t bo = (uint32_t)((warp_n * 32 + nh * 16 + b_n) * FPITCH +
                                         (ks * 16 + b_ko) * 2);
                ldsm4(bf[nh], stage + GA + bo);
            }
#pragma unroll
            for (int nh = 0; nh < 2; nh++)
#pragma unroll
                for (int mt = 0; mt < 2; mt++) {
                    mmaf16(acc[mt][nh * 2 + 0], af[mt], &bf[nh][0]);
                    mmaf16(acc[mt][nh * 2 + 1], af[mt], &bf[nh][2]);
                }
        }

        if (kb + 1 < NKB) {
            if (kb + 2 < NKB) CP_WAIT1(); else CP_WAIT0();
            __syncthreads();
        }
    }

    if (EPI) {
#pragma unroll
        for (int mt = 0; mt < 2; mt++) {
#pragma unroll
            for (int j = 0; j < 4; j++) {
                float* d = acc[mt][j];
                int n = n0 + warp_n * 32 + j * 8 + tg * 2;
                int sq = n >> 10, hh2 = (n >> 6) & 15, dd = n & 63;
                int r0 = m0 + warp_m * 32 + mt * 16 + g;
                float v0 = d[0], v1 = d[1], v2 = d[2], v3 = d[3];
                if (sq < 2) { v0 = phi(v0); v1 = phi(v1); v2 = phi(v2); v3 = phi(v3); }
                *(uint32_t*)&g_qkv[sq][hh2][r0][dd]     = packh2(v0, v1);
                *(uint32_t*)&g_qkv[sq][hh2][r0 + 8][dd] = packh2(v2, v3);
            }
        }
    } else {
#pragma unroll
        for (int mt = 0; mt < 2; mt++) {
#pragma unroll
            for (int j = 0; j < 4; j++) {
                float* d = acc[mt][j];
                int r0 = m0 + warp_m * 32 + mt * 16 + g;
                int col = n0 + warp_n * 32 + j * 8 + tg * 2;
                *(float2*)(C + (size_t)r0 * N + col)       = make_float2(d[0], d[1]);
                *(float2*)(C + (size_t)(r0 + 8) * N + col) = make_float2(d[2], d[3]);
            }
        }
    }
}

// ============================================================================
// chunk_sums via fp16 mma (unchanged)
// ============================================================================
#define CSK 144
#define CSV 176
#define OFF_CK 0
#define OFF_CV (128 * CSK)
#define CS_SMEM (OFF_CV + 128 * CSV)

__global__ __launch_bounds__(128) void chunk_sums() {
    extern __shared__ char smc[];
    const uint32_t sb = smem_u32(smc);
    const int blk = blockIdx.x;
    const int h = blk >> 4, cc = blk & 15;
    const int t0 = cc * CHUNK;
    const int tid = threadIdx.x;
    const int w = tid >> 5, lid = tid & 31;

#pragma unroll
    for (int j = 0; j < 8; j++) {
        int cid = tid + j * 128;
        int row = cid >> 3, c = cid & 7;
        CP16(sb + OFF_CK + row * CSK + c * 16, &g_qkv[1][h][t0 + row][0] + c * 8);
    }
#pragma unroll
    for (int j = 0; j < 8; j++) {
        int cid = tid + j * 128;
        int row = cid >> 3, c = cid & 7;
        CP16(sb + OFF_CV + row * CSV + c * 16, &g_qkv[2][h][t0 + row][0] + c * 8);
    }
    *(uint4*)(smc + OFF_CV + tid * CSV + 128) = make_uint4(0x00003C00u, 0u, 0u, 0u);
    *(uint4*)(smc + OFF_CV + tid * CSV + 144) = make_uint4(0u, 0u, 0u, 0u);
    CP_COMMIT();
    CP_WAIT0();
    __syncthreads();

    const int at_row = (lid & 7) + ((lid >> 4) << 3);
    const int at_co  = ((lid >> 3) & 1) * 8;
    const int bt_row = lid & 15;
    const int bt_co  = (lid >> 4) << 3;
    const int g = lid >> 2, tq = lid & 3;

    float acc[5][2][4];
#pragma unroll
    for (int fg = 0; fg < 5; fg++)
#pragma unroll
        for (int hf = 0; hf < 2; hf++)
#pragma unroll
            for (int e = 0; e < 4; e++) acc[fg][hf][e] = 0.f;

#pragma unroll
    for (int ks = 0; ks < 8; ks++) {
        uint32_t af[4];
        ldsm4t(af, sb + OFF_CK + (uint32_t)((ks * 16 + at_row) * CSK + (w * 16 + at_co) * 2));
#pragma unroll
        for (int fg = 0; fg < 5; fg++) {
            uint32_t bf[4];
            ldsm4t(bf, sb + OFF_CV + (uint32_t)((ks * 16 + bt_row) * CSV + (fg * 16 + bt_co) * 2));
            mmaf16(acc[fg][0], af, &bf[0]);
            mmaf16(acc[fg][1], af, &bf[2]);
        }
    }

    float* Sout = g_Sc + (size_t)blk * HS * SCP;
#pragma unroll
    for (int fg = 0; fg < 5; fg++)
#pragma unroll
        for (int hf = 0; hf < 2; hf++) {
            float* d = acc[fg][hf];
            int r = w * 16 + g;
            int col = fg * 16 + hf * 8 + tq * 2;
            *(float2*)&Sout[r * SCP + col]       = make_float2(d[0], d[1]);
            *(float2*)&Sout[(r + 8) * SCP + col] = make_float2(d[2], d[3]);
        }
}

// ---------------- exclusive prefix -> fp16 Sp (MLP-16 prefetch) ----------------
__global__ __launch_bounds__(256) void chunk_prefix() {
    int h = blockIdx.x / 20;
    int e = (blockIdx.x % 20) * 256 + threadIdx.x;
    const float* src = g_Sc + (size_t)h * NC * (HS * SCP) + e;
    __half* dst = g_sp + (size_t)h * NC * (HS * SCP) + e;

    float v[NC];
#pragma unroll
    for (int c = 0; c < NC; c++)
        v[c] = src[(size_t)c * (HS * SCP)];

    float run = 0.f;
#pragma unroll
    for (int c = 0; c < NC; c++) {
        dst[(size_t)c * (HS * SCP)] = __float2half_rn(run);
        run += v[c];
    }
}

// ============================================================================
// attention per chunk, single-limb fp16 mma (unchanged)
// ============================================================================
#define QVP 144
#define SPB 176
#define OFF_Q 0
#define OFF_K (1 * 128 * QVP)
#define OFF_V (2 * 128 * QVP)
#define OFF_SP (3 * 128 * QVP)
#define ATTN_SMEM_B (OFF_SP + 64 * SPB)

__global__ __launch_bounds__(256, 2) void attn_mma() {
    extern __shared__ char smc[];
    const uint32_t sb = smem_u32(smc);

    const int blk = blockIdx.x;
    const int h = blk >> 4, cc = blk & 15;
    const int t0g = cc * CHUNK;
    const int tid = threadIdx.x;
    const int w = tid >> 5, lid = tid & 31;

#pragma unroll
    for (int j = 0; j < 12; j++) {
        int chunkid = tid + j * 256;
        int buf = chunkid >> 10;
        int within = chunkid & 1023;
        int row = within >> 3, c = within & 7;
        CP16(sb + buf * (128 * QVP) + row * QVP + c * 16,
             &g_qkv[buf][h][t0g + row][0] + c * 8);
    }
#pragma unroll
    for (int j = 0; j < 3; j++) {
        int chunkid = tid + j * 256;
        if (chunkid < 640) {
            int row = chunkid / 10, c = chunkid % 10;
            CP16(sb + OFF_SP + row * SPB + c * 16,
                 g_sp + (size_t)blk * (HS * SCP) + row * SCP + c * 8);
        }
    }
    CP_COMMIT();
    CP_WAIT0();
    __syncthreads();

    const int a_row  = lid & 15;
    const int a_koff = (lid >> 4) * 8;
    const int b_n    = (lid & 7) + ((lid >> 4) << 3);
    const int b_ko   = ((lid >> 3) & 1) * 8;
    const int t_row  = lid & 15;
    const int t_col  = ((lid >> 4) << 3);
    const int g = lid >> 2, tq = lid & 3;

    float ca[16][4];
#pragma unroll
    for (int j = 0; j < 16; j++)
#pragma unroll
        for (int e = 0; e < 4; e++) ca[j][e] = 0.f;

#pragma unroll
    for (int ks = 0; ks < 4; ks++) {
        uint32_t aq[4];
        ldsm4(aq, sb + OFF_Q + (uint32_t)((w * 16 + a_row) * QVP + (ks * 16 + a_koff) * 2));
#pragma unroll
        for (int sg = 0; sg < 8; sg++) {
            uint32_t bk[4];
            ldsm4(bk, sb + OFF_K + (uint32_t)((sg * 16 + b_n) * QVP + (ks * 16 + b_ko) * 2));
            mmaf16(ca[sg * 2 + 0], aq, &bk[0]);
            mmaf16(ca[sg * 2 + 1], aq, &bk[2]);
        }
    }

    const int row_lo = w * 16 + g, row_hi = row_lo + 8;
    float s_lo = 0.f, s_hi = 0.f;
#pragma unroll
    for (int j = 0; j < 16; j++) {
        int c0 = j * 8 + tq * 2;
        if (c0     > row_lo) ca[j][0] = 0.f;
        if (c0 + 1 > row_lo) ca[j][1] = 0.f;
        if (c0     > row_hi) ca[j][2] = 0.f;
        if (c0 + 1 > row_hi) ca[j][3] = 0.f;
        s_lo += ca[j][0] + ca[j][1];
        s_hi += ca[j][2] + ca[j][3];
    }
    s_lo += __shfl_xor_sync(0xffffffffu, s_lo, 1);
    s_lo += __shfl_xor_sync(0xffffffffu, s_lo, 2);
    s_hi += __shfl_xor_sync(0xffffffffu, s_hi, 1);
    s_hi += __shfl_xor_sync(0xffffffffu, s_hi, 2);

    float co[10][4];
#pragma unroll
    for (int j = 0; j < 10; j++)
#pragma unroll
        for (int e = 0; e < 4; e++) co[j][e] = 0.f;

#pragma unroll
    for (int ks2 = 0; ks2 < 8; ks2++) {
        uint32_t af[4];
        af[0] = packh2(ca[ks2 * 2 + 0][0], ca[ks2 * 2 + 0][1]);
        af[1] = packh2(ca[ks2 * 2 + 0][2], ca[ks2 * 2 + 0][3]);
        af[2] = packh2(ca[ks2 * 2 + 1][0], ca[ks2 * 2 + 1][1]);
        af[3] = packh2(ca[ks2 * 2 + 1][2], ca[ks2 * 2 + 1][3]);
#pragma unroll
        for (int fg = 0; fg < 4; fg++) {
            uint32_t bv[4];
            ldsm4t(bv, sb + OFF_V + (uint32_t)((ks2 * 16 + t_row) * QVP + (fg * 16 + t_col) * 2));
            mmaf16(co[fg * 2 + 0], af, &bv[0]);
            mmaf16(co[fg * 2 + 1], af, &bv[2]);
        }
    }

#pragma unroll
    for (int ks = 0; ks < 4; ks++) {
        uint32_t aq[4];
        ldsm4(aq, sb + OFF_Q + (uint32_t)((w * 16 + a_row) * QVP + (ks * 16 + a_koff) * 2));
#pragma unroll
        for (int fg = 0; fg < 5; fg++) {
            uint32_t bs[4];
            ldsm4t(bs, sb + OFF_SP + (uint32_t)((ks * 16 + t_row) * SPB + (fg * 16 + t_col) * 2));
            mmaf16(co[fg * 2 + 0], aq, &bs[0]);
            mmaf16(co[fg * 2 + 1], aq, &bs[2]);
        }
    }

    float qz_lo = __shfl_sync(0xffffffffu, co[8][0], lid & ~3);
    float qz_hi = __shfl_sync(0xffffffffu, co[8][2], lid & ~3);
    float inv_lo = 1.f / (s_lo + qz_lo + EPSF);
    float inv_hi = 1.f / (s_hi + qz_hi + EPSF);

#pragma unroll
    for (int j = 0; j < 8; j++) {
        int col = h * HS + j * 8 + tq * 2;
        size_t i_lo = (size_t)(t0g + row_lo) * D_MODEL + col;
        size_t i_hi = (size_t)(t0g + row_hi) * D_MODEL + col;
        *(uint32_t*)(g_xh + i_lo) = packh2(co[j][0] * inv_lo, co[j][1] * inv_lo);
        *(uint32_t*)(g_xh + i_hi) = packh2(co[j][2] * inv_hi, co[j][3] * inv_hi);
    }
}

// ---------------- launch ----------------
extern "C" void kernel_launch(void* const* d_in, const int* in_sizes, int n_in,
                              void* d_out, int out_size) {
    const float* x     = (const float*)d_in[0];
    const float* w_qkv = (const float*)d_in[1];
    const float* w_out = (const float*)d_in[2];
    float* out = (float*)d_out;

    __half *xh, *w1, *w2;
    cudaGetSymbolAddress((void**)&xh, g_xh);
    cudaGetSymbolAddress((void**)&w1, g_w1);
    cudaGetSymbolAddress((void**)&w2, g_w2);

    cudaFuncSetAttribute(gemmT<1>, cudaFuncAttributeMaxDynamicSharedMemorySize, GSM);
    cudaFuncSetAttribute(gemmT<0>, cudaFuncAttributeMaxDynamicSharedMemorySize, GSM);
    cudaFuncSetAttribute(chunk_sums, cudaFuncAttributeMaxDynamicSharedMemorySize, CS_SMEM);
    cudaFuncSetAttribute(attn_mma,   cudaFuncAttributeMaxDynamicSharedMemorySize, ATTN_SMEM_B);

    cvt_all<<<CVT_TOTAL / 256, 256>>>(x, w_qkv, w_out);

    // GEMM1: qkv = x @ w_qkv^T  (64x128 tiles, 768 CTAs)
    dim3 g1(3 * D_MODEL / 128, T_LEN / 64);    // (24, 32)
    gemmT<1><<<g1, 256, GSM>>>(xh, w1, nullptr, T_LEN, 3 * D_MODEL, D_MODEL);

    chunk_sums<<<H_NUM * NC, 128, CS_SMEM>>>();
    chunk_prefix<<<H_NUM * 20, 256>>>();
    attn_mma<<<H_NUM * NC, 256, ATTN_SMEM_B>>>();

    // GEMM2: out = xo @ w_out^T (64x128 tiles, 256 CTAs)
    dim3 g2(D_MODEL / 128, T_LEN / 64);        // (8, 32)
    gemmT<0><<<g2, 256, GSM>>>(xh, w2, out, T_LEN, D_MODEL, D_MODEL);
}

// round 15
// speedup vs baseline: 1.5997x; 1.5997x over previous
#include <cuda_runtime.h>
#include <cuda_bf16.h>
#include <cuda_fp16.h>
#include <cstdint>

#define T_LEN 2048
#define D_MODEL 1024
#define H_NUM 16
#define HS 64
#define CHUNK 128
#define NC 16
#define EPSF 1e-6f
#define SCP 80

// ---------------- scratch ----------------
__device__ float g_Sc [H_NUM * NC * HS * SCP];
__device__ __align__(16) __half g_sp[H_NUM * NC * HS * SCP];     // prefix, fp16

__device__ __align__(16) __half g_qkv[3][H_NUM][T_LEN][HS];      // phi(q),phi(k),v fp16

__device__ __align__(16) __half g_xh[T_LEN * D_MODEL];           // x, then xo
__device__ __align__(16) __half g_w1[3 * D_MODEL * D_MODEL];
__device__ __align__(16) __half g_w2[D_MODEL * D_MODEL];

__device__ __forceinline__ float phi(float x) {
    return x > 0.f ? x + 1.f : expf(x);
}
__device__ __forceinline__ uint32_t packh2(float a, float b) {
    return (uint32_t)__half_as_ushort(__float2half_rn(a)) |
           ((uint32_t)__half_as_ushort(__float2half_rn(b)) << 16);
}

// fused fp32 -> fp16 for x, w_qkv, w_out (ranges in float4 chunks)
#define CVT_X  524288
#define CVT_W1 786432
#define CVT_W2 262144
#define CVT_TOTAL (CVT_X + CVT_W1 + CVT_W2)
__global__ __launch_bounds__(256) void cvt_all(const float* __restrict__ x,
                                               const float* __restrict__ w1,
                                               const float* __restrict__ w2) {
    int i = blockIdx.x * 256 + threadIdx.x;
    const float* s;
    __half* d;
    int off;
    if (i < CVT_X)                { s = x;  d = g_xh; off = i; }
    else if (i < CVT_X + CVT_W1)  { s = w1; d = g_w1; off = i - CVT_X; }
    else                          { s = w2; d = g_w2; off = i - CVT_X - CVT_W1; }
    float4 v = ((const float4*)s)[off];
    ((uint2*)d)[off] = make_uint2(packh2(v.x, v.y), packh2(v.z, v.w));
}

// ---------------- mma helpers ----------------
__device__ __forceinline__ uint32_t smem_u32(const void* p) {
    uint32_t a;
    asm("{ .reg .u64 t; cvta.to.shared.u64 t, %1; cvt.u32.u64 %0, t; }" : "=r"(a) : "l"(p));
    return a;
}
__device__ __forceinline__ void ldsm4(uint32_t* r, uint32_t addr) {
    asm volatile("ldmatrix.sync.aligned.m8n8.x4.shared.b16 {%0,%1,%2,%3}, [%4];"
                 : "=r"(r[0]), "=r"(r[1]), "=r"(r[2]), "=r"(r[3]) : "r"(addr));
}
__device__ __forceinline__ void ldsm4t(uint32_t* r, uint32_t addr) {
    asm volatile("ldmatrix.sync.aligned.m8n8.x4.trans.shared.b16 {%0,%1,%2,%3}, [%4];"
                 : "=r"(r[0]), "=r"(r[1]), "=r"(r[2]), "=r"(r[3]) : "r"(addr));
}
__device__ __forceinline__ void mmaf16(float* d, const uint32_t* a, const uint32_t* b) {
    asm volatile("mma.sync.aligned.m16n8k16.row.col.f32.f16.f16.f32 "
                 "{%0,%1,%2,%3},{%4,%5,%6,%7},{%8,%9},{%0,%1,%2,%3};"
                 : "+f"(d[0]), "+f"(d[1]), "+f"(d[2]), "+f"(d[3])
                 : "r"(a[0]), "r"(a[1]), "r"(a[2]), "r"(a[3]), "r"(b[0]), "r"(b[1]));
}
#define CP16(dst, src) \
    asm volatile("cp.async.cg.shared.global [%0], [%1], 16;" :: "r"(dst), "l"(src) : "memory")
#define CP_COMMIT() asm volatile("cp.async.commit_group;" ::: "memory")
#define CP_WAIT0()  asm volatile("cp.async.wait_group 0;" ::: "memory")
#define CP_WAIT1()  asm volatile("cp.async.wait_group 1;" ::: "memory")

// ============================================================================
// GEMM1: fp16, CTA 128x128, 8 warps 32x64, BK=64, 3-stage pipeline, 2 CTA/SM.
// EPI=1: fused phi + fp16 store -> g_qkv. EPI=0: fp32 C.
// ============================================================================
#define FPITCH 144
#define FTILE (128 * FPITCH)
#define FSTAGE (2 * FTILE)
#define GSMF (3 * FSTAGE)

template<int EPI>
__global__ __launch_bounds__(256, 2) void gemm_fp16(
        const __half* __restrict__ A, const __half* __restrict__ B,
        float* __restrict__ C, int M, int N, int K) {
    extern __shared__ char smem[];
    const uint32_t sb = smem_u32(smem);

    const int tid = threadIdx.x;
    const int wid = tid >> 5, lid = tid & 31;
    const int warp_m = wid & 3, warp_n = wid >> 2;
    const int m0 = blockIdx.y * 128, n0 = blockIdx.x * 128;
    const int NKB = K >> 6;

    const int a_row  = lid & 15;
    const int a_koff = (lid >> 4) * 8;
    const int b_n    = (lid & 7) + ((lid >> 4) << 3);
    const int b_ko   = ((lid >> 3) & 1) * 8;
    const int g = lid >> 2, tg = lid & 3;

    float acc[2][8][4];
#pragma unroll
    for (int i = 0; i < 2; i++)
#pragma unroll
        for (int j = 0; j < 8; j++)
#pragma unroll
            for (int k = 0; k < 4; k++) acc[i][j][k] = 0.f;

    auto load_st = [&](uint32_t stg, int kb) {
#pragma unroll
        for (int j = 0; j < 8; j++) {
            int chunkid = tid + j * 256;
            int tile = chunkid >> 10;
            int within = chunkid & 1023;
            int row = within >> 3, c = within & 7;
            const __half* src = (tile ? B + (size_t)(n0 + row) * K
                                      : A + (size_t)(m0 + row) * K) + kb * 64 + c * 8;
            CP16(stg + tile * FTILE + row * FPITCH + c * 16, src);
        }
        CP_COMMIT();
    };

    load_st(sb, 0);
    load_st(sb + FSTAGE, 1);
    CP_WAIT1();
    __syncthreads();

#pragma unroll 1
    for (int kb = 0; kb < NKB; kb++) {
        if (kb + 2 < NKB) load_st(sb + ((kb + 2) % 3) * FSTAGE, kb + 2);

        const uint32_t stage = sb + (kb % 3) * FSTAGE;
        const uint32_t tA = stage;
        const uint32_t tB = stage + FTILE;

#pragma unroll
        for (int ks = 0; ks < 4; ks++) {
            uint32_t af[2][4];
#pragma unroll
            for (int mt = 0; mt < 2; mt++) {
                uint32_t ao = (uint32_t)((warp_m * 32 + mt * 16 + a_row) * FPITCH +
                                         (ks * 16 + a_koff) * 2);
                ldsm4(af[mt], tA + ao);
            }
            uint32_t bf[4][4];
#pragma unroll
            for (int ng = 0; ng < 4; ng++) {
                uint32_t bo = (uint32_t)((warp_n * 64 + ng * 16 + b_n) * FPITCH +
                                         (ks * 16 + b_ko) * 2);
                ldsm4(bf[ng], tB + bo);
            }
#pragma unroll
            for (int ng = 0; ng < 4; ng++)
#pragma unroll
                for (int mt = 0; mt < 2; mt++) {
                    mmaf16(acc[mt][ng * 2 + 0], af[mt], &bf[ng][0]);
                    mmaf16(acc[mt][ng * 2 + 1], af[mt], &bf[ng][2]);
                }
        }

        if (kb + 1 < NKB) {
            if (kb + 2 < NKB) CP_WAIT1(); else CP_WAIT0();
            __syncthreads();
        }
    }

    if (EPI) {
#pragma unroll
        for (int mt = 0; mt < 2; mt++) {
#pragma unroll
            for (int j = 0; j < 8; j++) {
                float* d = acc[mt][j];
                int n = n0 + warp_n * 64 + j * 8 + tg * 2;
                int sq = n >> 10, hh2 = (n >> 6) & 15, dd = n & 63;
                int r0 = m0 + warp_m * 32 + mt * 16 + g;
                float v0 = d[0], v1 = d[1], v2 = d[2], v3 = d[3];
                if (sq < 2) { v0 = phi(v0); v1 = phi(v1); v2 = phi(v2); v3 = phi(v3); }
                *(uint32_t*)&g_qkv[sq][hh2][r0][dd]     = packh2(v0, v1);
                *(uint32_t*)&g_qkv[sq][hh2][r0 + 8][dd] = packh2(v2, v3);
            }
        }
    } else {
#pragma unroll
        for (int mt = 0; mt < 2; mt++) {
#pragma unroll
            for (int j = 0; j < 8; j++) {
                float* d = acc[mt][j];
                int r0 = m0 + warp_m * 32 + mt * 16 + g;
                int col = n0 + warp_n * 64 + j * 8 + tg * 2;
                *(float2*)(C + (size_t)r0 * N + col)       = make_float2(d[0], d[1]);
                *(float2*)(C + (size_t)(r0 + 8) * N + col) = make_float2(d[2], d[3]);
            }
        }
    }
}

// ============================================================================
// GEMM2: fp16, CTA 64x128, 8 warps 32x32, BK=64, 3-stage, 2 CTA/SM.
// ============================================================================
#define G2A (64 * FPITCH)
#define G2B (128 * FPITCH)
#define G2STG (G2A + G2B)
#define GSM2 (3 * G2STG)

__global__ __launch_bounds__(256, 2) void gemm2_fp16(
        const __half* __restrict__ A, const __half* __restrict__ B,
        float* __restrict__ C, int M, int N, int K) {
    extern __shared__ char smem[];
    const uint32_t sb = smem_u32(smem);

    const int tid = threadIdx.x;
    const int wid = tid >> 5, lid = tid & 31;
    const int warp_m = wid & 1, warp_n = wid >> 1;
    const int m0 = blockIdx.y * 64, n0 = blockIdx.x * 128;
    const int NKB = K >> 6;

    const int a_row  = lid & 15;
    const int a_koff = (lid >> 4) * 8;
    const int b_n    = (lid & 7) + ((lid >> 4) << 3);
    const int b_ko   = ((lid >> 3) & 1) * 8;
    const int g = lid >> 2, tg = lid & 3;

    float acc[2][4][4];
#pragma unroll
    for (int i = 0; i < 2; i++)
#pragma unroll
        for (int j = 0; j < 4; j++)
#pragma unroll
            for (int k = 0; k < 4; k++) acc[i][j][k] = 0.f;

    auto load_st = [&](uint32_t stg, int kb) {
#pragma unroll
        for (int j = 0; j < 6; j++) {
            int chunkid = tid + j * 256;
            if (chunkid < 512) {
                int row = chunkid >> 3, c = chunkid & 7;
                CP16(stg + row * FPITCH + c * 16,
                     A + (size_t)(m0 + row) * K + kb * 64 + c * 8);
            } else {
                int cid = chunkid - 512;
                int row = cid >> 3, c = cid & 7;
                CP16(stg + G2A + row * FPITCH + c * 16,
                     B + (size_t)(n0 + row) * K + kb * 64 + c * 8);
            }
        }
        CP_COMMIT();
    };

    load_st(sb, 0);
    load_st(sb + G2STG, 1);
    CP_WAIT1();
    __syncthreads();

#pragma unroll 1
    for (int kb = 0; kb < NKB; kb++) {
        if (kb + 2 < NKB) load_st(sb + ((kb + 2) % 3) * G2STG, kb + 2);

        const uint32_t stage = sb + (kb % 3) * G2STG;

#pragma unroll
        for (int ks = 0; ks < 4; ks++) {
            uint32_t af[2][4];
#pragma unroll
            for (int mt = 0; mt < 2; mt++) {
                uint32_t ao = (uint32_t)((warp_m * 32 + mt * 16 + a_row) * FPITCH +
                                         (ks * 16 + a_koff) * 2);
                ldsm4(af[mt], stage + ao);
            }
            uint32_t bf[2][4];
#pragma unroll
            for (int nh = 0; nh < 2; nh++) {
                uint32_t bo = (uint32_t)((warp_n * 32 + nh * 16 + b_n) * FPITCH +
                                         (ks * 16 + b_ko) * 2);
                ldsm4(bf[nh], stage + G2A + bo);
            }
#pragma unroll
            for (int nh = 0; nh < 2; nh++)
#pragma unroll
                for (int mt = 0; mt < 2; mt++) {
                    mmaf16(acc[mt][nh * 2 + 0], af[mt], &bf[nh][0]);
                    mmaf16(acc[mt][nh * 2 + 1], af[mt], &bf[nh][2]);
                }
        }

        if (kb + 1 < NKB) {
            if (kb + 2 < NKB) CP_WAIT1(); else CP_WAIT0();
            __syncthreads();
        }
    }

#pragma unroll
    for (int mt = 0; mt < 2; mt++) {
#pragma unroll
        for (int j = 0; j < 4; j++) {
            float* d = acc[mt][j];
            int r0 = m0 + warp_m * 32 + mt * 16 + g;
            int col = n0 + warp_n * 32 + j * 8 + tg * 2;
            *(float2*)(C + (size_t)r0 * N + col)       = make_float2(d[0], d[1]);
            *(float2*)(C + (size_t)(r0 + 8) * N + col) = make_float2(d[2], d[3]);
        }
    }
}

// ============================================================================
// chunk_sums via fp16 mma
// ============================================================================
#define CSK 144
#define CSV 176
#define OFF_CK 0
#define OFF_CV (128 * CSK)
#define CS_SMEM (OFF_CV + 128 * CSV)

__global__ __launch_bounds__(128) void chunk_sums() {
    extern __shared__ char smc[];
    const uint32_t sb = smem_u32(smc);
    const int blk = blockIdx.x;
    const int h = blk >> 4, cc = blk & 15;
    const int t0 = cc * CHUNK;
    const int tid = threadIdx.x;
    const int w = tid >> 5, lid = tid & 31;

#pragma unroll
    for (int j = 0; j < 8; j++) {
        int cid = tid + j * 128;
        int row = cid >> 3, c = cid & 7;
        CP16(sb + OFF_CK + row * CSK + c * 16, &g_qkv[1][h][t0 + row][0] + c * 8);
    }
#pragma unroll
    for (int j = 0; j < 8; j++) {
        int cid = tid + j * 128;
        int row = cid >> 3, c = cid & 7;
        CP16(sb + OFF_CV + row * CSV + c * 16, &g_qkv[2][h][t0 + row][0] + c * 8);
    }
    *(uint4*)(smc + OFF_CV + tid * CSV + 128) = make_uint4(0x00003C00u, 0u, 0u, 0u);
    *(uint4*)(smc + OFF_CV + tid * CSV + 144) = make_uint4(0u, 0u, 0u, 0u);
    CP_COMMIT();
    CP_WAIT0();
    __syncthreads();

    const int at_row = (lid & 7) + ((lid >> 4) << 3);
    const int at_co  = ((lid >> 3) & 1) * 8;
    const int bt_row = lid & 15;
    const int bt_co  = (lid >> 4) << 3;
    const int g = lid >> 2, tq = lid & 3;

    float acc[5][2][4];
#pragma unroll
    for (int fg = 0; fg < 5; fg++)
#pragma unroll
        for (int hf = 0; hf < 2; hf++)
#pragma unroll
            for (int e = 0; e < 4; e++) acc[fg][hf][e] = 0.f;

#pragma unroll
    for (int ks = 0; ks < 8; ks++) {
        uint32_t af[4];
        ldsm4t(af, sb + OFF_CK + (uint32_t)((ks * 16 + at_row) * CSK + (w * 16 + at_co) * 2));
#pragma unroll
        for (int fg = 0; fg < 5; fg++) {
            uint32_t bf[4];
            ldsm4t(bf, sb + OFF_CV + (uint32_t)((ks * 16 + bt_row) * CSV + (fg * 16 + bt_co) * 2));
            mmaf16(acc[fg][0], af, &bf[0]);
            mmaf16(acc[fg][1], af, &bf[2]);
        }
    }

    float* Sout = g_Sc + (size_t)blk * HS * SCP;
#pragma unroll
    for (int fg = 0; fg < 5; fg++)
#pragma unroll
        for (int hf = 0; hf < 2; hf++) {
            float* d = acc[fg][hf];
            int r = w * 16 + g;
            int col = fg * 16 + hf * 8 + tq * 2;
            *(float2*)&Sout[r * SCP + col]       = make_float2(d[0], d[1]);
            *(float2*)&Sout[(r + 8) * SCP + col] = make_float2(d[2], d[3]);
        }
}

// ---------------- exclusive prefix -> fp16 Sp (MLP-16 prefetch) ----------------
__global__ __launch_bounds__(256) void chunk_prefix() {
    int h = blockIdx.x / 20;
    int e = (blockIdx.x % 20) * 256 + threadIdx.x;
    const float* src = g_Sc + (size_t)h * NC * (HS * SCP) + e;
    __half* dst = g_sp + (size_t)h * NC * (HS * SCP) + e;

    float v[NC];
#pragma unroll
    for (int c = 0; c < NC; c++)
        v[c] = src[(size_t)c * (HS * SCP)];

    float run = 0.f;
#pragma unroll
    for (int c = 0; c < NC; c++) {
        dst[(size_t)c * (HS * SCP)] = __float2half_rn(run);
        run += v[c];
    }
}

// ============================================================================
// attention per chunk, single-limb fp16 mma
// ============================================================================
#define QVP 144
#define SPB 176
#define OFF_Q 0
#define OFF_K (1 * 128 * QVP)
#define OFF_V (2 * 128 * QVP)
#define OFF_SP (3 * 128 * QVP)
#define ATTN_SMEM_B (OFF_SP + 64 * SPB)

__global__ __launch_bounds__(256, 2) void attn_mma() {
    extern __shared__ char smc[];
    const uint32_t sb = smem_u32(smc);

    const int blk = blockIdx.x;
    const int h = blk >> 4, cc = blk & 15;
    const int t0g = cc * CHUNK;
    const int tid = threadIdx.x;
    const int w = tid >> 5, lid = tid & 31;

#pragma unroll
    for (int j = 0; j < 12; j++) {
        int chunkid = tid + j * 256;
        int buf = chunkid >> 10;
        int within = chunkid & 1023;
        int row = within >> 3, c = within & 7;
        CP16(sb + buf * (128 * QVP) + row * QVP + c * 16,
             &g_qkv[buf][h][t0g + row][0] + c * 8);
    }
#pragma unroll
    for (int j = 0; j < 3; j++) {
        int chunkid = tid + j * 256;
        if (chunkid < 640) {
            int row = chunkid / 10, c = chunkid % 10;
            CP16(sb + OFF_SP + row * SPB + c * 16,
                 g_sp + (size_t)blk * (HS * SCP) + row * SCP + c * 8);
        }
    }
    CP_COMMIT();
    CP_WAIT0();
    __syncthreads();

    const int a_row  = lid & 15;
    const int a_koff = (lid >> 4) * 8;
    const int b_n    = (lid & 7) + ((lid >> 4) << 3);
    const int b_ko   = ((lid >> 3) & 1) * 8;
    const int t_row  = lid & 15;
    const int t_col  = ((lid >> 4) << 3);
    const int g = lid >> 2, tq = lid & 3;

    float ca[16][4];
#pragma unroll
    for (int j = 0; j < 16; j++)
#pragma unroll
        for (int e = 0; e < 4; e++) ca[j][e] = 0.f;

#pragma unroll
    for (int ks = 0; ks < 4; ks++) {
        uint32_t aq[4];
        ldsm4(aq, sb + OFF_Q + (uint32_t)((w * 16 + a_row) * QVP + (ks * 16 + a_koff) * 2));
#pragma unroll
        for (int sg = 0; sg < 8; sg++) {
            uint32_t bk[4];
            ldsm4(bk, sb + OFF_K + (uint32_t)((sg * 16 + b_n) * QVP + (ks * 16 + b_ko) * 2));
            mmaf16(ca[sg * 2 + 0], aq, &bk[0]);
            mmaf16(ca[sg * 2 + 1], aq, &bk[2]);
        }
    }

    const int row_lo = w * 16 + g, row_hi = row_lo + 8;
    float s_lo = 0.f, s_hi = 0.f;
#pragma unroll
    for (int j = 0; j < 16; j++) {
        int c0 = j * 8 + tq * 2;
        if (c0     > row_lo) ca[j][0] = 0.f;
        if (c0 + 1 > row_lo) ca[j][1] = 0.f;
        if (c0     > row_hi) ca[j][2] = 0.f;
        if (c0 + 1 > row_hi) ca[j][3] = 0.f;
        s_lo += ca[j][0] + ca[j][1];
        s_hi += ca[j][2] + ca[j][3];
    }
    s_lo += __shfl_xor_sync(0xffffffffu, s_lo, 1);
    s_lo += __shfl_xor_sync(0xffffffffu, s_lo, 2);
    s_hi += __shfl_xor_sync(0xffffffffu, s_hi, 1);
    s_hi += __shfl_xor_sync(0xffffffffu, s_hi, 2);

    float co[10][4];
#pragma unroll
    for (int j = 0; j < 10; j++)
#pragma unroll
        for (int e = 0; e < 4; e++) co[j][e] = 0.f;

#pragma unroll
    for (int ks2 = 0; ks2 < 8; ks2++) {
        uint32_t af[4];
        af[0] = packh2(ca[ks2 * 2 + 0][0], ca[ks2 * 2 + 0][1]);
        af[1] = packh2(ca[ks2 * 2 + 0][2], ca[ks2 * 2 + 0][3]);
        af[2] = packh2(ca[ks2 * 2 + 1][0], ca[ks2 * 2 + 1][1]);
        af[3] = packh2(ca[ks2 * 2 + 1][2], ca[ks2 * 2 + 1][3]);
#pragma unroll
        for (int fg = 0; fg < 4; fg++) {
            uint32_t bv[4];
            ldsm4t(bv, sb + OFF_V + (uint32_t)((ks2 * 16 + t_row) * QVP + (fg * 16 + t_col) * 2));
            mmaf16(co[fg * 2 + 0], af, &bv[0]);
            mmaf16(co[fg * 2 + 1], af, &bv[2]);
        }
    }

#pragma unroll
    for (int ks = 0; ks < 4; ks++) {
        uint32_t aq[4];
        ldsm4(aq, sb + OFF_Q + (uint32_t)((w * 16 + a_row) * QVP + (ks * 16 + a_koff) * 2));
#pragma unroll
        for (int fg = 0; fg < 5; fg++) {
            uint32_t bs[4];
            ldsm4t(bs, sb + OFF_SP + (uint32_t)((ks * 16 + t_row) * SPB + (fg * 16 + t_col) * 2));
            mmaf16(co[fg * 2 + 0], aq, &bs[0]);
            mmaf16(co[fg * 2 + 1], aq, &bs[2]);
        }
    }

    float qz_lo = __shfl_sync(0xffffffffu, co[8][0], lid & ~3);
    float qz_hi = __shfl_sync(0xffffffffu, co[8][2], lid & ~3);
    float inv_lo = 1.f / (s_lo + qz_lo + EPSF);
    float inv_hi = 1.f / (s_hi + qz_hi + EPSF);

#pragma unroll
    for (int j = 0; j < 8; j++) {
        int col = h * HS + j * 8 + tq * 2;
        size_t i_lo = (size_t)(t0g + row_lo) * D_MODEL + col;
        size_t i_hi = (size_t)(t0g + row_hi) * D_MODEL + col;
        *(uint32_t*)(g_xh + i_lo) = packh2(co[j][0] * inv_lo, co[j][1] * inv_lo);
        *(uint32_t*)(g_xh + i_hi) = packh2(co[j][2] * inv_hi, co[j][3] * inv_hi);
    }
}

// ---------------- launch ----------------
extern "C" void kernel_launch(void* const* d_in, const int* in_sizes, int n_in,
                              void* d_out, int out_size) {
    const float* x     = (const float*)d_in[0];
    const float* w_qkv = (const float*)d_in[1];
    const float* w_out = (const float*)d_in[2];
    float* out = (float*)d_out;

    __half *xh, *w1, *w2;
    cudaGetSymbolAddress((void**)&xh, g_xh);
    cudaGetSymbolAddress((void**)&w1, g_w1);
    cudaGetSymbolAddress((void**)&w2, g_w2);

    cudaFuncSetAttribute(gemm_fp16<1>, cudaFuncAttributeMaxDynamicSharedMemorySize, GSMF);
    cudaFuncSetAttribute(gemm_fp16<0>, cudaFuncAttributeMaxDynamicSharedMemorySize, GSMF);
    cudaFuncSetAttribute(gemm2_fp16,   cudaFuncAttributeMaxDynamicSharedMemorySize, GSM2);
    cudaFuncSetAttribute(chunk_sums,   cudaFuncAttributeMaxDynamicSharedMemorySize, CS_SMEM);
    cudaFuncSetAttribute(attn_mma,     cudaFuncAttributeMaxDynamicSharedMemorySize, ATTN_SMEM_B);

    cvt_all<<<CVT_TOTAL / 256, 256>>>(x, w_qkv, w_out);

    // GEMM1: qkv = x @ w_qkv^T (128x128 tiles — R13 best config)
    dim3 g1(3 * D_MODEL / 128, T_LEN / 128);   // (24, 16)
    gemm_fp16<1><<<g1, 256, GSMF>>>(xh, w1, nullptr, T_LEN, 3 * D_MODEL, D_MODEL);

    chunk_sums<<<H_NUM * NC, 128, CS_SMEM>>>();
    chunk_prefix<<<H_NUM * 20, 256>>>();
    attn_mma<<<H_NUM * NC, 256, ATTN_SMEM_B>>>();

    // GEMM2: out = xo @ w_out^T (64x128 tiles)
    dim3 g2(D_MODEL / 128, T_LEN / 64);        // (8, 32)
    gemm2_fp16<<<g2, 256, GSM2>>>(xh, w2, out, T_LEN, D_MODEL, D_MODEL);
}